// round 8
// baseline (speedup 1.0000x reference)
#include <cuda_runtime.h>
#include <math.h>

#define N_ 16384
#define D_ 2048
#define H_ 1024

// fp32(exp(-100)) = 27 * 2^-149 (subnormal), bit pattern 0x0000001B.
#define CLIP_P_BITS 27u

#define GRID_  2048
#define NPROD  512          // blocks 0..511: 2 Mu rows each
#define SCALAR_BLK 512      // block 512: Sd/W scalar reductions
#define NARRIVE (NPROD + 1) // threshold publishes after 513 arrivals

// ---------------- scratch (device globals; no allocation allowed) ----------
__device__ float g_mu2[H_];        // ||mu_h||^2 (fallback path)
__device__ int   g_maxmu2_bits;    // atomicMax over mu2 (nonneg -> int order ok)
__device__ int   g_count;          // producer arrival counter
__device__ int   g_done;           // all-block completion counter (for reset)
__device__ float g_maxsd2;
__device__ float g_zconst;         // exact subnormal z for a clipped row
__device__ float g_yconst;         // y for a clipped row
__device__ float g_x2thresh;       // row clips if (partial) x2 > this
__device__ volatile int g_ready;   // threshold published flag

// Non-FTZ fp32 ops (immune to any -ftz / fast-math compile flags).
__device__ __forceinline__ float mul_rn(float a, float b) {
    float c; asm("mul.rn.f32 %0, %1, %2;" : "=f"(c) : "f"(a), "f"(b)); return c;
}
__device__ __forceinline__ float add_rn(float a, float b) {
    float c; asm("add.rn.f32 %0, %1, %2;" : "=f"(c) : "f"(a), "f"(b)); return c;
}

// ---------------- single fused kernel ---------------------------------------
// Deadlock-safety: all producer blocks (0..512) fit in scheduling wave 1
// (>=740 resident blocks at occ>=4 on 148 SMs) and never wait on anything.
// Consumers issue ALL their heavy traffic (stage-1 x loads + speculative p
// stores) before spinning, so the spin only covers the producers' ~1-2 us.
__global__ void __launch_bounds__(256, 5) k_all(const float* __restrict__ x,
                                                const float* __restrict__ Mu,
                                                const float* __restrict__ Sd,
                                                const float* __restrict__ W,
                                                float* __restrict__ y,
                                                float* __restrict__ p) {
    __shared__ float sh[256];
    __shared__ float sh2[256];
    const int t    = threadIdx.x;
    const int bid  = blockIdx.x;
    const int warp = t >> 5;
    const int lane = t & 31;

    // ============== producer section (blocks 0..512 only) ===================
    if (bid < NPROD) {
        // 2 Mu rows per block: threads 0-127 -> row 2b, 128-255 -> row 2b+1
        const int half = t >> 7;           // 0 or 1
        const int l    = t & 127;
        const int row  = bid * 2 + half;
        const float4* r = (const float4*)(Mu + (size_t)row * D_);
        float s = 0.0f;
#pragma unroll
        for (int i = 0; i < 4; i++) {
            float4 v = r[l + 128 * i];
            s += v.x * v.x + v.y * v.y + v.z * v.z + v.w * v.w;
        }
#pragma unroll
        for (int o = 16; o > 0; o >>= 1) s += __shfl_xor_sync(0xFFFFFFFFu, s, o);
        if (lane == 0) sh[warp] = s;       // warps 0-3 row0, 4-7 row1
        __syncthreads();
        if (t == 0 || t == 128) {
            float m2 = sh[half * 4] + sh[half * 4 + 1]
                     + sh[half * 4 + 2] + sh[half * 4 + 3];
            g_mu2[row] = m2;
            atomicMax(&g_maxmu2_bits, __float_as_int(m2));
        }
        __syncthreads();
        if (t == 0) {
            __threadfence();
            atomicAdd(&g_count, 1);        // arrival (publisher logic below)
        }
    } else if (bid == SCALAR_BLK) {
        // scalar reductions: maxsd2 + exact subnormal z over 1024
        float msd = 0.0f;
        const float C = __uint_as_float(CLIP_P_BITS);
        float zp = 0.0f;
#pragma unroll
        for (int i = 0; i < 4; i++) {
            float sd = Sd[t + 256 * i];
            msd = fmaxf(msd, sd * sd);
            // exact: products are multiples of 2^-149, |sum| << 2^-126,
            // so fp32 adds are exact and order-independent.
            zp = add_rn(zp, mul_rn(C, W[t + 256 * i]));
        }
        sh[t] = msd;
        sh2[t] = zp;
        __syncthreads();
        for (int o = 128; o > 0; o >>= 1) {
            if (t < o) {
                sh[t] = fmaxf(sh[t], sh[t + o]);
                sh2[t] = add_rn(sh2[t], sh2[t + o]);
            }
            __syncthreads();
        }
        if (t == 0) {
            g_maxsd2 = sh[0];
            float z = sh2[0];
            g_zconst = z;
            float tt = mul_rn(2.0f / 3.0f, z);                // subnormal-safe
            float th = (fabsf(tt) < 1e-5f) ? tt : tanhf(tt);  // tanh(x)==x tiny
            g_yconst = mul_rn(1.7159f, th);
            __threadfence();
            atomicAdd(&g_count, 1);
        }
    }

    // publisher: thread 0 of whichever block made the LAST arrival
    if (bid <= SCALAR_BLK && t == 0) {
        // re-read the counter; the block whose arrival completed the set
        // publishes. (atomicAdd returns old value; check inside arrival.)
    }
    // NOTE: publication is handled via the arrival's return value:
    //   done in the arrival sites above would need the return; do it here
    //   cleanly by re-checking with a dedicated CAS-free pattern:
    if (bid <= SCALAR_BLK && t == 0) {
        // Only the last arriver sees g_count == NARRIVE and wins the publish
        // via atomicExch on a one-shot ticket (g_ready doubles as ticket:
        // 0 = unpublished). All producer writes are fenced before arrivals.
        if (atomicAdd(&g_count, 0) == NARRIVE && g_ready == 0) {
            // races here are benign: all candidates compute identical values
            __threadfence();
            float maxmu2 = __int_as_float(g_maxmu2_bits);
            float maxsd2 = g_maxsd2;
            // Row n clips for ALL h iff dist(n,h) > 200*sd_h^2 for all h.
            // Cauchy-Schwarz: dist >= (sqrt(x2)-sqrt(mu2_h))^2 when x2>mu2_h.
            // Margins cover our fp error AND the reference's fp32 GEMM error.
            float rhs = sqrtf(maxmu2) + sqrtf(200.0f * maxsd2 * 1.001f + 4.0f);
            g_x2thresh = rhs * rhs;
            __threadfence();
            g_ready = 1;
            __threadfence();
        }
    }

    // ============== consumer section (ALL blocks) ============================
    const int n = bid * 8 + warp;
    const float4* xr = (const float4*)(x + (size_t)n * D_);
    float4* prow = (float4*)(p + (size_t)n * H_);

    // Stage 1: lower bound on ||x_n||^2 from first 768 elems
    float4 v[6];
#pragma unroll
    for (int i = 0; i < 6; i++) v[i] = xr[lane + 32 * i];

    // Speculative fill: p[n,:] = exp(-100) (input-independent value).
    const float C = __uint_as_float(CLIP_P_BITS);
    const float4 c4 = make_float4(C, C, C, C);
#pragma unroll
    for (int i = 0; i < 8; i++) __stcs(prow + lane + 32 * i, c4);

    float s = 0.0f;
#pragma unroll
    for (int i = 0; i < 6; i++)
        s += v[i].x * v[i].x + v[i].y * v[i].y + v[i].z * v[i].z + v[i].w * v[i].w;
#pragma unroll
    for (int o = 16; o > 0; o >>= 1) s += __shfl_xor_sync(0xFFFFFFFFu, s, o);

    // spin for the threshold (producers are all wave-1 and never wait)
    if (lane == 0) {
        while (g_ready == 0) __nanosleep(128);
    }
    __syncwarp();
    __threadfence();   // acquire
    const float thresh = g_x2thresh;

    bool clipped = (s > thresh);
    if (!clipped) {
        // Stage 2: exact x2 (remaining 1280 elems; rare)
        float s2 = 0.0f;
#pragma unroll
        for (int i = 6; i < 16; i++) {
            float4 w4 = __ldcs(xr + lane + 32 * i);
            s2 += w4.x * w4.x + w4.y * w4.y + w4.z * w4.z + w4.w * w4.w;
        }
#pragma unroll
        for (int o = 16; o > 0; o >>= 1) s2 += __shfl_xor_sync(0xFFFFFFFFu, s2, o);
        s += s2;
        clipped = (s > thresh);
    }

    if (clipped) {
        if (lane == 0) y[n] = g_yconst;   // speculative p row already correct
    } else {
        // Exact fallback for an unproven row (insurance; ~never runs).
        // Overwrites are same-lane as the speculative fill (lane owns h with
        // ((h>>2)&31)==lane) => same-thread program order, no race.
        const float* xs = (const float*)xr;
        float z = 0.0f;
#pragma unroll 1
        for (int h = 0; h < H_; h++) {
            const float* mr = Mu + (size_t)h * D_;
            float dot = 0.0f;
#pragma unroll 1
            for (int k = lane; k < D_; k += 32) dot += xs[k] * mr[k];
#pragma unroll
            for (int o = 16; o > 0; o >>= 1)
                dot += __shfl_xor_sync(0xFFFFFFFFu, dot, o);
            float sd = Sd[h];
            float power = -0.5f * (s - 2.0f * dot + g_mu2[h]) / (sd * sd);
            power = fminf(fmaxf(power, -100.0f), 40.0f);
            float pv = expf(power);
            if (lane == ((h >> 2) & 31)) p[(size_t)n * H_ + h] = pv;
            if (lane == 0) z += pv * W[h];
        }
        if (lane == 0) {
            float tt = mul_rn(2.0f / 3.0f, z);
            float th = (fabsf(tt) < 1e-5f) ? tt : tanhf(tt);
            y[n] = mul_rn(1.7159f, th);
        }
    }

    // self-reset for the next graph replay: the LAST block to finish clears
    // the flags (every block has finished reading g_ready/thresh by the time
    // it increments g_done).
    __syncthreads();
    if (t == 0) {
        __threadfence();
        int c = atomicAdd(&g_done, 1);
        if (c == GRID_ - 1) {
            g_ready = 0;
            g_count = 0;
            g_done = 0;
            g_maxmu2_bits = 0;
            __threadfence();
        }
    }
}

extern "C" void kernel_launch(void* const* d_in, const int* in_sizes, int n_in,
                              void* d_out, int out_size) {
    const float* x  = (const float*)d_in[0];
    const float* Mu = (const float*)d_in[1];
    const float* Sd = (const float*)d_in[2];
    const float* W  = (const float*)d_in[3];
    float* y = (float*)d_out;          // first N_ elements
    float* p = (float*)d_out + N_;     // then N_*H_ elements

    k_all<<<GRID_, 256>>>(x, Mu, Sd, W, y, p);
}

// round 9
// speedup vs baseline: 1.8537x; 1.8537x over previous
#include <cuda_runtime.h>
#include <math.h>

#define N_ 16384
#define D_ 2048
#define H_ 1024

// fp32(exp(-100)) = 27 * 2^-149 (subnormal), bit pattern 0x0000001B.
#define CLIP_P_BITS 27u

// Stage prefixes (elements of each x row): stage-1 = 640 (5 float4/lane),
// stage-2 extends to 1024 (3 more float4/lane), stage-3 = exact fallback.
#define P1 640
#define P2 1024

// ---------------- scratch (device globals; no allocation allowed) ----------
__device__ int   g_max640_bits;    // atomicMax of prefix-640 mu norms (>=0)
__device__ int   g_max1024_bits;   // atomicMax of prefix-1024 mu norms (>=0)
__device__ int   g_count;          // last-block-done counter (self-resetting)
__device__ float g_maxsd2;
__device__ float g_zconst;         // exact subnormal z for a clipped row
__device__ float g_yconst;         // y for a clipped row
__device__ float g_th640;          // row clips if prefix-640 x2 > this
__device__ float g_th1024;         // row clips if prefix-1024 x2 > this

// Non-FTZ fp32 ops (immune to any -ftz / fast-math compile flags).
__device__ __forceinline__ float mul_rn(float a, float b) {
    float c; asm("mul.rn.f32 %0, %1, %2;" : "=f"(c) : "f"(a), "f"(b)); return c;
}
__device__ __forceinline__ float add_rn(float a, float b) {
    float c; asm("add.rn.f32 %0, %1, %2;" : "=f"(c) : "f"(a), "f"(b)); return c;
}

// ---------------- K1: prologue (PDL primary) --------------------------------
// 1024 blocks x 256 threads; one Mu row per block, but only the first 1024
// columns (4 MB total, not 8): the clip thresholds only need PREFIX norms.
__global__ void __launch_bounds__(256) k_pre(const float* __restrict__ Mu,
                                             const float* __restrict__ Sd,
                                             const float* __restrict__ W) {
    // Signal PDL dependents immediately: k_main may launch, stream its x
    // loads AND its speculative p stores while we compute.
    asm volatile("griddepcontrol.launch_dependents;" ::: "memory");

    __shared__ float sh[256];
    __shared__ float sh2[256];
    const int t = threadIdx.x;
    const int warp = t >> 5;
    const int lane = t & 31;
    const int row = blockIdx.x;

    // one float4 per thread covers Mu[row, 0:1024]
    const float4* r = (const float4*)(Mu + (size_t)row * D_);
    float4 v = r[t];
    float sq = v.x * v.x + v.y * v.y + v.z * v.z + v.w * v.w;
    float sq6 = (t < P1 / 4) ? sq : 0.0f;    // first 160 float4 = prefix 640
#pragma unroll
    for (int o = 16; o > 0; o >>= 1) {
        sq  += __shfl_xor_sync(0xFFFFFFFFu, sq, o);
        sq6 += __shfl_xor_sync(0xFFFFFFFFu, sq6, o);
    }
    if (lane == 0) { sh[warp] = sq6; sh2[warp] = sq; }
    __syncthreads();
    if (t == 0) {
        float m6 = 0.0f, m10 = 0.0f;
#pragma unroll
        for (int i = 0; i < 8; i++) { m6 += sh[i]; m10 += sh2[i]; }
        atomicMax(&g_max640_bits,  __float_as_int(m6));
        atomicMax(&g_max1024_bits, __float_as_int(m10));
    }
    __syncthreads();

    if (blockIdx.x == 0) {
        // maxsd2 + exact subnormal z over 1024 (4 per thread)
        float msd = 0.0f;
        const float C = __uint_as_float(CLIP_P_BITS);
        float zp = 0.0f;
#pragma unroll
        for (int i = 0; i < 4; i++) {
            float sd = Sd[t + 256 * i];
            msd = fmaxf(msd, sd * sd);
            // exact: products are multiples of 2^-149, |sum| << 2^-126,
            // so fp32 adds are exact and order-independent.
            zp = add_rn(zp, mul_rn(C, W[t + 256 * i]));
        }
        sh[t] = msd;
        sh2[t] = zp;
        __syncthreads();
        for (int o = 128; o > 0; o >>= 1) {
            if (t < o) {
                sh[t] = fmaxf(sh[t], sh[t + o]);
                sh2[t] = add_rn(sh2[t], sh2[t + o]);
            }
            __syncthreads();
        }
        if (t == 0) {
            g_maxsd2 = sh[0];
            float z = sh2[0];
            g_zconst = z;
            float tt = mul_rn(2.0f / 3.0f, z);                // subnormal-safe
            float th = (fabsf(tt) < 1e-5f) ? tt : tanhf(tt);  // tanh(x)==x tiny
            g_yconst = mul_rn(1.7159f, th);
        }
        __syncthreads();
    }

    if (t == 0) {
        __threadfence();
        int c = atomicAdd(&g_count, 1);
        if (c == (int)gridDim.x - 1) {   // last block: publish thresholds
            __threadfence();
            // For any coordinate-prefix S: dist(n,h) >= (||x_S||-||mu_h,S||)^2
            // when ||x_S|| > ||mu_h,S||. Row clips for all h if
            //   ||x_S|| > max_h||mu_h,S|| + sqrt(200*maxsd2*1.001 + 4)
            // (margins cover our fp error AND the reference's GEMM rounding).
            float R = sqrtf(200.0f * g_maxsd2 * 1.001f + 4.0f);
            float a6  = sqrtf(__int_as_float(g_max640_bits))  + R;
            float a10 = sqrtf(__int_as_float(g_max1024_bits)) + R;
            g_th640  = a6 * a6;
            g_th1024 = a10 * a10;
            // reset for next graph replay
            g_max640_bits = 0;
            g_max1024_bits = 0;
            g_count = 0;
            __threadfence();
        }
    }
}

// ---------------- K2: fused main (PDL secondary) ----------------------------
// 2048 blocks x 256 threads; warp per x row.
// Stage-1 x loads (prefix 640) and the SPECULATIVE p-row fill (value C is
// input-independent) are issued BEFORE griddepcontrol.wait, hiding k_pre.
// Stage-2 (prefix 1024, ~5% of rows) and stage-3 (exact fallback, ~never)
// run after the wait.
__global__ void __launch_bounds__(256, 5) k_main(const float* __restrict__ x,
                                                 const float* __restrict__ Mu,
                                                 const float* __restrict__ Sd,
                                                 const float* __restrict__ W,
                                                 float* __restrict__ y,
                                                 float* __restrict__ p) {
    const int warp = threadIdx.x >> 5;
    const int lane = threadIdx.x & 31;
    const int n    = blockIdx.x * 8 + warp;
    const float4* xr = (const float4*)(x + (size_t)n * D_);
    float4* prow = (float4*)(p + (size_t)n * H_);

    // Stage 1: lower bound on ||x_n||^2 from the first 640 elems
    // (sums of squares are monotone, so any prefix is a valid lower bound)
    float4 v[5];
#pragma unroll
    for (int i = 0; i < 5; i++) v[i] = xr[lane + 32 * i];

    // Speculative fill: p[n,:] = exp(-100). Correct for ~every row; a rare
    // unproven row is recomputed and overwritten after verification.
    const float C = __uint_as_float(CLIP_P_BITS);
    const float4 c4 = make_float4(C, C, C, C);
#pragma unroll
    for (int i = 0; i < 8; i++) __stcs(prow + lane + 32 * i, c4);

    float s = 0.0f;
#pragma unroll
    for (int i = 0; i < 5; i++)
        s += v[i].x * v[i].x + v[i].y * v[i].y + v[i].z * v[i].z + v[i].w * v[i].w;
#pragma unroll
    for (int o = 16; o > 0; o >>= 1) s += __shfl_xor_sync(0xFFFFFFFFu, s, o);

    // Wait for k_pre completion (+ memory visibility). HW wait, not a spin.
    asm volatile("griddepcontrol.wait;" ::: "memory");

    bool clipped = (s > g_th640);
    if (!clipped) {
        // Stage 2: extend to prefix 1024 (3 more float4/lane; ~5% of rows)
        float s2 = 0.0f;
#pragma unroll
        for (int i = 5; i < 8; i++) {
            float4 w4 = __ldcs(xr + lane + 32 * i);
            s2 += w4.x * w4.x + w4.y * w4.y + w4.z * w4.z + w4.w * w4.w;
        }
#pragma unroll
        for (int o = 16; o > 0; o >>= 1) s2 += __shfl_xor_sync(0xFFFFFFFFu, s2, o);
        s += s2;
        clipped = (s > g_th1024);
    }

    if (clipped) {
        if (lane == 0) y[n] = g_yconst;   // speculative p row already correct
    } else {
        // Stage 3: exact fallback for an unproven row (insurance; ~never).
        // Computes full x2, and mu2 inline per h (no precomputed tables).
        // Overwrites are same-lane as the speculative fill (lane owns h with
        // ((h>>2)&31)==lane) => same-thread program order, no race.
        float s3 = 0.0f;
#pragma unroll 1
        for (int i = 8; i < 16; i++) {
            float4 w4 = __ldcs(xr + lane + 32 * i);
            s3 += w4.x * w4.x + w4.y * w4.y + w4.z * w4.z + w4.w * w4.w;
        }
#pragma unroll
        for (int o = 16; o > 0; o >>= 1) s3 += __shfl_xor_sync(0xFFFFFFFFu, s3, o);
        s += s3;   // exact ||x_n||^2

        const float* xs = (const float*)xr;
        float z = 0.0f;
#pragma unroll 1
        for (int h = 0; h < H_; h++) {
            const float* mr = Mu + (size_t)h * D_;
            float dot = 0.0f, m2 = 0.0f;
#pragma unroll 1
            for (int k = lane; k < D_; k += 32) {
                float mv = mr[k];
                dot += xs[k] * mv;
                m2  += mv * mv;
            }
#pragma unroll
            for (int o = 16; o > 0; o >>= 1) {
                dot += __shfl_xor_sync(0xFFFFFFFFu, dot, o);
                m2  += __shfl_xor_sync(0xFFFFFFFFu, m2, o);
            }
            float sd = Sd[h];
            float power = -0.5f * (s - 2.0f * dot + m2) / (sd * sd);
            power = fminf(fmaxf(power, -100.0f), 40.0f);
            float pv = expf(power);
            if (lane == ((h >> 2) & 31)) p[(size_t)n * H_ + h] = pv;
            if (lane == 0) z += pv * W[h];
        }
        if (lane == 0) {
            float tt = mul_rn(2.0f / 3.0f, z);
            float th = (fabsf(tt) < 1e-5f) ? tt : tanhf(tt);
            y[n] = mul_rn(1.7159f, th);
        }
    }
}

extern "C" void kernel_launch(void* const* d_in, const int* in_sizes, int n_in,
                              void* d_out, int out_size) {
    const float* x  = (const float*)d_in[0];
    const float* Mu = (const float*)d_in[1];
    const float* Sd = (const float*)d_in[2];
    const float* W  = (const float*)d_in[3];
    float* y = (float*)d_out;          // first N_ elements
    float* p = (float*)d_out + N_;     // then N_*H_ elements

    k_pre<<<1024, 256>>>(Mu, Sd, W);

    // k_main with Programmatic Dependent Launch: it begins executing while
    // k_pre is still running; it synchronizes in-kernel via griddepcontrol.wait.
    cudaLaunchAttribute attrs[1];
    attrs[0].id = cudaLaunchAttributeProgrammaticStreamSerialization;
    attrs[0].val.programmaticStreamSerializationAllowed = 1;

    cudaLaunchConfig_t cfg = {};
    cfg.gridDim  = dim3(2048, 1, 1);
    cfg.blockDim = dim3(256, 1, 1);
    cfg.dynamicSmemBytes = 0;
    cfg.stream = 0;            // legacy default stream (the captured stream)
    cfg.attrs = attrs;
    cfg.numAttrs = 1;

    cudaLaunchKernelEx(&cfg, k_main, x, Mu, Sd, W, y, p);
}